// round 5
// baseline (speedup 1.0000x reference)
#include <cuda_runtime.h>
#include <cstdint>

#define B_ROWS   524288
#define D_DIM    64
#define NQ       (B_ROWS * 16)        // total float4 quads = 8388608
#define THREADS  256
#define GRID     592                  // 148 SMs * 4 blocks
#define STRIDE   (GRID * THREADS)     // 151552 quads; multiple of 32

__device__ float g_part[GRID];

__device__ __forceinline__ float row_epilogue(
    float m, float s, float q, int lab, float lb,
    const float* __restrict__ linear_p,
    const float* __restrict__ bias_p,
    const float* __restrict__ centers)
{
    m += lb;
    const int l3 = lab * 3;
    const float A0 = __ldg(linear_p + l3 + 0);
    const float A1 = __ldg(linear_p + l3 + 1);
    const float A2 = __ldg(linear_p + l3 + 2);
    const float B0 = __ldg(bias_p   + l3 + 0);
    const float B1 = __ldg(bias_p   + l3 + 1);
    const float B2 = __ldg(bias_p   + l3 + 2);
    const float C0 = __ldg(centers  + l3 + 0);
    const float C1 = __ldg(centers  + l3 + 1);
    const float C2 = __ldg(centers  + l3 + 2);

    const float l0 = fmaf(m, A0, B0);
    const float l1 = fmaf(m, A1, B1);
    const float l2 = fmaf(m, A2, B2);
    const float mx = fmaxf(l0, fmaxf(l1, l2));
    const float e0 = __expf(l0 - mx);
    const float e1 = __expf(l1 - mx);
    const float e2 = __expf(l2 - mx);
    const float inv = 1.f / (e0 + e1 + e2);

    const float t0 = C0 * fmaf(64.f, C0, -2.f * s);
    const float t1 = C1 * fmaf(64.f, C1, -2.f * s);
    const float t2 = C2 * fmaf(64.f, C2, -2.f * s);
    return q + inv * (e0 * t0 + e1 * t1 + e2 * t2);
}

__global__ void __launch_bounds__(THREADS, 4) mcl_main(
    const float* __restrict__ x,
    const int*   __restrict__ labels,    // int32 on device (JAX x64 off)
    const float* __restrict__ lin_w,
    const float* __restrict__ lin_b,
    const float* __restrict__ linear_p,
    const float* __restrict__ bias_p,
    const float* __restrict__ centers)
{
    __shared__ float warp_acc[THREADS / 32];

    const int tid   = blockIdx.x * THREADS + threadIdx.x;
    const int c4    = tid & 15;                 // this thread's column quad, fixed
    const bool lead = (threadIdx.x & 15) == 0;  // lanes 0,16 of each warp

    const float4 w  = __ldg(((const float4*)lin_w) + c4);
    const float  lb = __ldg(lin_b);
    const float4* __restrict__ gx = (const float4*)x;

    float acc = 0.f;

    for (int g = tid; g < NQ; g += 2 * STRIDE) {
        const int g1 = g + STRIDE;
        const bool have2 = g1 < NQ;             // uniform across the warp

        // front-batch both loads (MLP=2) + label prefetch for leader lanes
        const float4 v0 = __ldg(gx + g);
        float4 v1 = make_float4(0.f, 0.f, 0.f, 0.f);
        if (have2) v1 = __ldg(gx + g1);
        int lab0 = 0, lab1 = 0;
        if (lead) {
            lab0 = min(max(__ldg(labels + (g >> 4)), 0), 999);
            if (have2) lab1 = min(max(__ldg(labels + (g1 >> 4)), 0), 999);
        }

        // ---- row 0: per-lane partials, 16-lane butterfly, leader epilogue
        {
            float m = v0.x * w.x;  m = fmaf(v0.y, w.y, m);
            m = fmaf(v0.z, w.z, m); m = fmaf(v0.w, w.w, m);
            float s = (v0.x + v0.y) + (v0.z + v0.w);
            float q = v0.x * v0.x;  q = fmaf(v0.y, v0.y, q);
            q = fmaf(v0.z, v0.z, q); q = fmaf(v0.w, v0.w, q);
            #pragma unroll
            for (int o = 8; o > 0; o >>= 1) {
                m += __shfl_xor_sync(0xffffffffu, m, o);
                s += __shfl_xor_sync(0xffffffffu, s, o);
                q += __shfl_xor_sync(0xffffffffu, q, o);
            }
            if (lead)
                acc += row_epilogue(m, s, q, lab0, lb, linear_p, bias_p, centers);
        }

        // ---- row 1
        if (have2) {
            float m = v1.x * w.x;  m = fmaf(v1.y, w.y, m);
            m = fmaf(v1.z, w.z, m); m = fmaf(v1.w, w.w, m);
            float s = (v1.x + v1.y) + (v1.z + v1.w);
            float q = v1.x * v1.x;  q = fmaf(v1.y, v1.y, q);
            q = fmaf(v1.z, v1.z, q); q = fmaf(v1.w, v1.w, q);
            #pragma unroll
            for (int o = 8; o > 0; o >>= 1) {
                m += __shfl_xor_sync(0xffffffffu, m, o);
                s += __shfl_xor_sync(0xffffffffu, s, o);
                q += __shfl_xor_sync(0xffffffffu, q, o);
            }
            if (lead)
                acc += row_epilogue(m, s, q, lab1, lb, linear_p, bias_p, centers);
        }
    }

    // block reduction (only lanes 0,16 carry nonzero acc; reduce all anyway)
    #pragma unroll
    for (int o = 16; o > 0; o >>= 1)
        acc += __shfl_xor_sync(0xffffffffu, acc, o);
    if ((threadIdx.x & 31) == 0)
        warp_acc[threadIdx.x >> 5] = acc;
    __syncthreads();
    if (threadIdx.x == 0) {
        float t = 0.f;
        #pragma unroll
        for (int i = 0; i < THREADS / 32; i++) t += warp_acc[i];
        g_part[blockIdx.x] = t;     // every slot rewritten each call: no init pass
    }
}

__global__ void __launch_bounds__(256) mcl_fin(float* __restrict__ out) {
    __shared__ double sd[8];
    double t = 0.0;
    for (int i = threadIdx.x; i < GRID; i += 256)
        t += (double)g_part[i];
    #pragma unroll
    for (int o = 16; o > 0; o >>= 1)
        t += __shfl_xor_sync(0xffffffffu, t, o);
    if ((threadIdx.x & 31) == 0)
        sd[threadIdx.x >> 5] = t;
    __syncthreads();
    if (threadIdx.x == 0) {
        double s = 0.0;
        #pragma unroll
        for (int i = 0; i < 8; i++) s += sd[i];
        out[0] = (float)(s / (double)B_ROWS);
    }
}

extern "C" void kernel_launch(void* const* d_in, const int* in_sizes, int n_in,
                              void* d_out, int out_size)
{
    const float* x        = (const float*)d_in[0];
    const int*   labels   = (const int*)d_in[1];
    const float* lin_w    = (const float*)d_in[2];
    const float* lin_b    = (const float*)d_in[3];
    const float* linear_p = (const float*)d_in[4];
    const float* bias_p   = (const float*)d_in[5];
    const float* centers  = (const float*)d_in[6];

    mcl_main<<<GRID, THREADS>>>(x, labels, lin_w, lin_b, linear_p, bias_p, centers);
    mcl_fin<<<1, 256>>>((float*)d_out);
}

// round 6
// speedup vs baseline: 1.4880x; 1.4880x over previous
#include <cuda_runtime.h>
#include <cstdint>

#define B_ROWS     524288
#define D_DIM      64
#define TILE       128
#define THREADS    128
#define GRID       444               // 148 SMs * 3 blocks (smem-limited)
#define NTILES     (B_ROWS / TILE)   // 4096
#define ROW_STRIDE 68                // pad 64->68 floats: conflict-free LDS.128
#define BUF_FLOATS (TILE * ROW_STRIDE)
#define SMEM_BYTES (2 * BUF_FLOATS * 4)   // 69632 B, double-buffered

__device__ float        g_part[GRID];
__device__ unsigned int g_count = 0;   // reset to 0 by last block every call

__device__ __forceinline__ void cp_async16(uint32_t saddr, const void* gptr) {
    asm volatile("cp.async.cg.shared.global [%0], [%1], 16;\n"
                 :: "r"(saddr), "l"(gptr) : "memory");
}

__device__ __forceinline__ void stage_tile(float* __restrict__ dst,
                                           const float4* __restrict__ gx,
                                           int tid)
{
    #pragma unroll
    for (int k = 0; k < 16; k++) {
        int f   = k * THREADS + tid;   // float4 index in tile
        int row = f >> 4;
        int c4  = f & 15;
        uint32_t saddr = (uint32_t)__cvta_generic_to_shared(
            dst + row * ROW_STRIDE + c4 * 4);
        cp_async16(saddr, gx + f);
    }
    asm volatile("cp.async.commit_group;\n" ::: "memory");
}

__global__ void __launch_bounds__(THREADS, 3) mcl_main(
    const float* __restrict__ x,
    const int*   __restrict__ labels,   // int32 on device
    const float* __restrict__ lin_w,
    const float* __restrict__ lin_b,
    const float* __restrict__ linear_p,
    const float* __restrict__ bias_p,
    const float* __restrict__ centers,
    float*       __restrict__ out)
{
    extern __shared__ __align__(16) float sx[];   // 2 * BUF_FLOATS
    __shared__ __align__(16) float sw[D_DIM];
    __shared__ float warp_acc[THREADS / 32];
    __shared__ bool  s_last;

    const int tid = threadIdx.x;
    const int bid = blockIdx.x;
    if (tid < D_DIM / 4)
        ((float4*)sw)[tid] = ((const float4*)lin_w)[tid];
    const float lb = __ldg(lin_b);

    // prologue: stage first tile into buffer 0
    stage_tile(sx, (const float4*)(x + (size_t)bid * TILE * D_DIM), tid);

    float acc = 0.f;
    int buf = 0;

    for (int tile = bid; tile < NTILES; tile += GRID) {
        const int nxt = tile + GRID;
        if (nxt < NTILES) {
            stage_tile(sx + (buf ^ 1) * BUF_FLOATS,
                       (const float4*)(x + (size_t)nxt * TILE * D_DIM), tid);
        }

        // label for this thread's row while tiles are in flight
        int lab = __ldg(&labels[tile * TILE + tid]);
        lab = min(max(lab, 0), 999);

        if (nxt < NTILES)
            asm volatile("cp.async.wait_group 1;\n" ::: "memory");
        else
            asm volatile("cp.async.wait_group 0;\n" ::: "memory");
        __syncthreads();

        // one thread per row: conflict-free LDS.128 sweep
        const float4* xr = (const float4*)(sx + buf * BUF_FLOATS + tid * ROW_STRIDE);
        float m = 0.f, s = 0.f, q = 0.f;
        #pragma unroll
        for (int j = 0; j < 16; j++) {
            float4 v = xr[j];
            float4 w = ((const float4*)sw)[j];
            m = fmaf(v.x, w.x, m); m = fmaf(v.y, w.y, m);
            m = fmaf(v.z, w.z, m); m = fmaf(v.w, w.w, m);
            s += (v.x + v.y) + (v.z + v.w);
            q = fmaf(v.x, v.x, q); q = fmaf(v.y, v.y, q);
            q = fmaf(v.z, v.z, q); q = fmaf(v.w, v.w, q);
        }
        m += lb;

        const int l3 = lab * 3;
        const float A0 = __ldg(linear_p + l3 + 0);
        const float A1 = __ldg(linear_p + l3 + 1);
        const float A2 = __ldg(linear_p + l3 + 2);
        const float B0 = __ldg(bias_p   + l3 + 0);
        const float B1 = __ldg(bias_p   + l3 + 1);
        const float B2 = __ldg(bias_p   + l3 + 2);
        const float C0 = __ldg(centers  + l3 + 0);
        const float C1 = __ldg(centers  + l3 + 1);
        const float C2 = __ldg(centers  + l3 + 2);

        const float l0 = fmaf(m, A0, B0);
        const float l1 = fmaf(m, A1, B1);
        const float l2 = fmaf(m, A2, B2);
        const float mx = fmaxf(l0, fmaxf(l1, l2));
        const float e0 = __expf(l0 - mx);
        const float e1 = __expf(l1 - mx);
        const float e2 = __expf(l2 - mx);
        const float inv = 1.f / (e0 + e1 + e2);

        const float t0 = C0 * fmaf(64.f, C0, -2.f * s);
        const float t1 = C1 * fmaf(64.f, C1, -2.f * s);
        const float t2 = C2 * fmaf(64.f, C2, -2.f * s);
        acc += q + inv * (e0 * t0 + e1 * t1 + e2 * t2);

        __syncthreads();   // all reads of buf done before it is restaged next iter
        buf ^= 1;
    }

    // block reduction
    #pragma unroll
    for (int o = 16; o > 0; o >>= 1)
        acc += __shfl_xor_sync(0xffffffffu, acc, o);
    if ((tid & 31) == 0)
        warp_acc[tid >> 5] = acc;
    __syncthreads();
    if (tid == 0) {
        float t = 0.f;
        #pragma unroll
        for (int i = 0; i < THREADS / 32; i++) t += warp_acc[i];
        g_part[bid] = t;
        __threadfence();
        unsigned int old = atomicAdd(&g_count, 1u);
        s_last = (old == GRID - 1);
    }
    __syncthreads();

    // last block finalizes: fixed-order double reduction (deterministic)
    if (s_last && tid < 32) {
        double t = 0.0;
        for (int i = tid; i < GRID; i += 32)
            t += (double)g_part[i];
        #pragma unroll
        for (int o = 16; o > 0; o >>= 1)
            t += __shfl_xor_sync(0xffffffffu, t, o);
        if (tid == 0) {
            out[0] = (float)(t / (double)B_ROWS);
            g_count = 0;   // rearm for next graph replay
        }
    }
}

extern "C" void kernel_launch(void* const* d_in, const int* in_sizes, int n_in,
                              void* d_out, int out_size)
{
    const float* x        = (const float*)d_in[0];
    const int*   labels   = (const int*)d_in[1];
    const float* lin_w    = (const float*)d_in[2];
    const float* lin_b    = (const float*)d_in[3];
    const float* linear_p = (const float*)d_in[4];
    const float* bias_p   = (const float*)d_in[5];
    const float* centers  = (const float*)d_in[6];

    cudaFuncSetAttribute(mcl_main,
                         cudaFuncAttributeMaxDynamicSharedMemorySize, SMEM_BYTES);
    mcl_main<<<GRID, THREADS, SMEM_BYTES>>>(x, labels, lin_w, lin_b,
                                            linear_p, bias_p, centers,
                                            (float*)d_out);
}

// round 7
// speedup vs baseline: 1.6712x; 1.1231x over previous
#include <cuda_runtime.h>
#include <cstdint>

#define B_ROWS     524288
#define D_DIM      64
#define TILE       128
#define THREADS    128
#define GRID       296               // 148 SMs * 2 blocks (smem-limited)
#define NTILES     (B_ROWS / TILE)   // 4096
#define ROW_STRIDE 68                // pad 64->68 floats: conflict-free LDS.128
#define BUF_FLOATS (TILE * ROW_STRIDE)          // 8704
#define TAB_FLOATS 9000                          // 3 tables * 1000 * 3
#define SMEM_FLOATS (2 * BUF_FLOATS + TAB_FLOATS)
#define SMEM_BYTES  (SMEM_FLOATS * 4)            // 105632 B

__device__ float        g_part[GRID];
__device__ unsigned int g_count = 0;   // reset by last block every call

__device__ __forceinline__ void cp_async16(uint32_t saddr, const void* gptr) {
    asm volatile("cp.async.cg.shared.global [%0], [%1], 16;\n"
                 :: "r"(saddr), "l"(gptr) : "memory");
}

__device__ __forceinline__ void stage_tile(float* __restrict__ dst,
                                           const float4* __restrict__ gx,
                                           int tid)
{
    #pragma unroll
    for (int k = 0; k < 16; k++) {
        int f   = k * THREADS + tid;   // float4 index in tile
        int row = f >> 4;
        int c4  = f & 15;
        uint32_t saddr = (uint32_t)__cvta_generic_to_shared(
            dst + row * ROW_STRIDE + c4 * 4);
        cp_async16(saddr, gx + f);
    }
    asm volatile("cp.async.commit_group;\n" ::: "memory");
}

__global__ void __launch_bounds__(THREADS, 2) mcl_main(
    const float* __restrict__ x,
    const int*   __restrict__ labels,   // int32 on device
    const float* __restrict__ lin_w,
    const float* __restrict__ lin_b,
    const float* __restrict__ linear_p,
    const float* __restrict__ bias_p,
    const float* __restrict__ centers,
    float*       __restrict__ out)
{
    extern __shared__ __align__(16) float smem[];
    float* sx   = smem;                       // 2 * BUF_FLOATS
    float* stab = smem + 2 * BUF_FLOATS;      // [0:3000) A, [3000:6000) B, [6000:9000) C
    __shared__ __align__(16) float sw[D_DIM];
    __shared__ float warp_acc[THREADS / 32];
    __shared__ bool  s_last;

    const int tid = threadIdx.x;
    const int bid = blockIdx.x;

    // stage first tile immediately (cp.async group 0), then fill tables/weights
    stage_tile(sx, (const float4*)(x + (size_t)bid * TILE * D_DIM), tid);

    {   // tables: 3 * 750 float4, coalesced; overlaps with tile-0 fill
        const float4* gA = (const float4*)linear_p;
        const float4* gB = (const float4*)bias_p;
        const float4* gC = (const float4*)centers;
        float4* sA = (float4*)stab;
        float4* sB = (float4*)(stab + 3000);
        float4* sC = (float4*)(stab + 6000);
        for (int i = tid; i < 750; i += THREADS) {
            sA[i] = __ldg(gA + i);
            sB[i] = __ldg(gB + i);
            sC[i] = __ldg(gC + i);
        }
    }
    if (tid < D_DIM / 4)
        ((float4*)sw)[tid] = ((const float4*)lin_w)[tid];
    const float lb = __ldg(lin_b);

    float acc = 0.f;
    int buf = 0;

    for (int tile = bid; tile < NTILES; tile += GRID) {
        const int nxt = tile + GRID;
        if (nxt < NTILES) {
            stage_tile(sx + (buf ^ 1) * BUF_FLOATS,
                       (const float4*)(x + (size_t)nxt * TILE * D_DIM), tid);
        }

        int lab = __ldg(&labels[tile * TILE + tid]);
        lab = min(max(lab, 0), 999);

        if (nxt < NTILES)
            asm volatile("cp.async.wait_group 1;\n" ::: "memory");
        else
            asm volatile("cp.async.wait_group 0;\n" ::: "memory");
        __syncthreads();

        // one thread per row: conflict-free LDS.128 sweep
        const float4* xr = (const float4*)(sx + buf * BUF_FLOATS + tid * ROW_STRIDE);
        float m = 0.f, s = 0.f, q = 0.f;
        #pragma unroll
        for (int j = 0; j < 16; j++) {
            float4 v = xr[j];
            float4 w = ((const float4*)sw)[j];
            m = fmaf(v.x, w.x, m); m = fmaf(v.y, w.y, m);
            m = fmaf(v.z, w.z, m); m = fmaf(v.w, w.w, m);
            s += (v.x + v.y) + (v.z + v.w);
            q = fmaf(v.x, v.x, q); q = fmaf(v.y, v.y, q);
            q = fmaf(v.z, v.z, q); q = fmaf(v.w, v.w, q);
        }
        m += lb;

        // table gathers from shared (cheap scattered LDS, no L1TEX wavefront storm)
        const int l3 = lab * 3;
        const float A0 = stab[l3 + 0];
        const float A1 = stab[l3 + 1];
        const float A2 = stab[l3 + 2];
        const float B0 = stab[3000 + l3 + 0];
        const float B1 = stab[3000 + l3 + 1];
        const float B2 = stab[3000 + l3 + 2];
        const float C0 = stab[6000 + l3 + 0];
        const float C1 = stab[6000 + l3 + 1];
        const float C2 = stab[6000 + l3 + 2];

        const float l0 = fmaf(m, A0, B0);
        const float l1 = fmaf(m, A1, B1);
        const float l2 = fmaf(m, A2, B2);
        const float mx = fmaxf(l0, fmaxf(l1, l2));
        const float e0 = __expf(l0 - mx);
        const float e1 = __expf(l1 - mx);
        const float e2 = __expf(l2 - mx);
        const float inv = 1.f / (e0 + e1 + e2);

        const float t0 = C0 * fmaf(64.f, C0, -2.f * s);
        const float t1 = C1 * fmaf(64.f, C1, -2.f * s);
        const float t2 = C2 * fmaf(64.f, C2, -2.f * s);
        acc += q + inv * (e0 * t0 + e1 * t1 + e2 * t2);

        __syncthreads();   // all reads of buf done before restage next iter
        buf ^= 1;
    }

    // block reduction
    #pragma unroll
    for (int o = 16; o > 0; o >>= 1)
        acc += __shfl_xor_sync(0xffffffffu, acc, o);
    if ((tid & 31) == 0)
        warp_acc[tid >> 5] = acc;
    __syncthreads();
    if (tid == 0) {
        float t = 0.f;
        #pragma unroll
        for (int i = 0; i < THREADS / 32; i++) t += warp_acc[i];
        g_part[bid] = t;
        __threadfence();
        unsigned int old = atomicAdd(&g_count, 1u);
        s_last = (old == GRID - 1);
    }
    __syncthreads();

    // last block finalizes: fixed-order double reduction (deterministic)
    if (s_last && tid < 32) {
        double t = 0.0;
        for (int i = tid; i < GRID; i += 32)
            t += (double)g_part[i];
        #pragma unroll
        for (int o = 16; o > 0; o >>= 1)
            t += __shfl_xor_sync(0xffffffffu, t, o);
        if (tid == 0) {
            out[0] = (float)(t / (double)B_ROWS);
            g_count = 0;   // rearm for next graph replay
        }
    }
}

extern "C" void kernel_launch(void* const* d_in, const int* in_sizes, int n_in,
                              void* d_out, int out_size)
{
    const float* x        = (const float*)d_in[0];
    const int*   labels   = (const int*)d_in[1];
    const float* lin_w    = (const float*)d_in[2];
    const float* lin_b    = (const float*)d_in[3];
    const float* linear_p = (const float*)d_in[4];
    const float* bias_p   = (const float*)d_in[5];
    const float* centers  = (const float*)d_in[6];

    cudaFuncSetAttribute(mcl_main,
                         cudaFuncAttributeMaxDynamicSharedMemorySize, SMEM_BYTES);
    mcl_main<<<GRID, THREADS, SMEM_BYTES>>>(x, labels, lin_w, lin_b,
                                            linear_p, bias_p, centers,
                                            (float*)d_out);
}

// round 8
// speedup vs baseline: 1.7807x; 1.0656x over previous
#include <cuda_runtime.h>
#include <cstdint>

#define B_ROWS     524288
#define D_DIM      64
#define TILE       256
#define THREADS    256
#define GRID       148               // 1 block per SM
#define NTILES     (B_ROWS / TILE)   // 2048
#define ROW_STRIDE 68                // pad 64->68 floats: conflict-free LDS.128
#define BUF_FLOATS (TILE * ROW_STRIDE)          // 17408
#define TAB_FLOATS 9000                          // 3 tables * 1000 * 3
#define SMEM_FLOATS (2 * BUF_FLOATS + TAB_FLOATS)
#define SMEM_BYTES  (SMEM_FLOATS * 4)            // 175264 B

__device__ float        g_part[GRID];
__device__ unsigned int g_count = 0;   // reset by last block every call

__device__ __forceinline__ void cp_async16(uint32_t saddr, const void* gptr) {
    asm volatile("cp.async.cg.shared.global [%0], [%1], 16;\n"
                 :: "r"(saddr), "l"(gptr) : "memory");
}

__device__ __forceinline__ void stage_tile(float* __restrict__ dst,
                                           const float4* __restrict__ gx,
                                           int tid)
{
    #pragma unroll
    for (int k = 0; k < 16; k++) {
        int f   = k * THREADS + tid;   // float4 index in tile (4096 total)
        int row = f >> 4;
        int c4  = f & 15;
        uint32_t saddr = (uint32_t)__cvta_generic_to_shared(
            dst + row * ROW_STRIDE + c4 * 4);
        cp_async16(saddr, gx + f);
    }
    asm volatile("cp.async.commit_group;\n" ::: "memory");
}

__global__ void __launch_bounds__(THREADS, 1) mcl_main(
    const float* __restrict__ x,
    const int*   __restrict__ labels,   // int32 on device
    const float* __restrict__ lin_w,
    const float* __restrict__ lin_b,
    const float* __restrict__ linear_p,
    const float* __restrict__ bias_p,
    const float* __restrict__ centers,
    float*       __restrict__ out)
{
    extern __shared__ __align__(16) float smem[];
    float* sx   = smem;                       // 2 * BUF_FLOATS
    float* stab = smem + 2 * BUF_FLOATS;      // [0:3000) A, [3000:6000) B, [6000:9000) C
    __shared__ __align__(16) float sw[D_DIM];
    __shared__ float warp_acc[THREADS / 32];
    __shared__ bool  s_last;

    const int tid = threadIdx.x;
    const int bid = blockIdx.x;

    // stage first tile immediately, then fill tables/weights (overlapped)
    stage_tile(sx, (const float4*)(x + (size_t)bid * TILE * D_DIM), tid);

    {   // tables: 3 * 750 float4, coalesced
        const float4* gA = (const float4*)linear_p;
        const float4* gB = (const float4*)bias_p;
        const float4* gC = (const float4*)centers;
        float4* sA = (float4*)stab;
        float4* sB = (float4*)(stab + 3000);
        float4* sC = (float4*)(stab + 6000);
        for (int i = tid; i < 750; i += THREADS) {
            sA[i] = __ldg(gA + i);
            sB[i] = __ldg(gB + i);
            sC[i] = __ldg(gC + i);
        }
    }
    if (tid < D_DIM / 4)
        ((float4*)sw)[tid] = ((const float4*)lin_w)[tid];
    const float lb = __ldg(lin_b);

    float acc = 0.f;
    int buf = 0;

    for (int tile = bid; tile < NTILES; tile += GRID) {
        const int nxt = tile + GRID;
        if (nxt < NTILES) {
            stage_tile(sx + (buf ^ 1) * BUF_FLOATS,
                       (const float4*)(x + (size_t)nxt * TILE * D_DIM), tid);
        }

        int lab = __ldg(&labels[tile * TILE + tid]);
        lab = min(max(lab, 0), 999);

        if (nxt < NTILES)
            asm volatile("cp.async.wait_group 1;\n" ::: "memory");
        else
            asm volatile("cp.async.wait_group 0;\n" ::: "memory");
        __syncthreads();

        // one thread per row: conflict-free LDS.128 sweep
        const float4* xr = (const float4*)(sx + buf * BUF_FLOATS + tid * ROW_STRIDE);
        float m = 0.f, s = 0.f, q = 0.f;
        #pragma unroll
        for (int j = 0; j < 16; j++) {
            float4 v = xr[j];
            float4 w = ((const float4*)sw)[j];
            m = fmaf(v.x, w.x, m); m = fmaf(v.y, w.y, m);
            m = fmaf(v.z, w.z, m); m = fmaf(v.w, w.w, m);
            s += (v.x + v.y) + (v.z + v.w);
            q = fmaf(v.x, v.x, q); q = fmaf(v.y, v.y, q);
            q = fmaf(v.z, v.z, q); q = fmaf(v.w, v.w, q);
        }
        m += lb;

        // table gathers from shared (random banks, ~4-way worst case: cheap)
        const int l3 = lab * 3;
        const float A0 = stab[l3 + 0];
        const float A1 = stab[l3 + 1];
        const float A2 = stab[l3 + 2];
        const float B0 = stab[3000 + l3 + 0];
        const float B1 = stab[3000 + l3 + 1];
        const float B2 = stab[3000 + l3 + 2];
        const float C0 = stab[6000 + l3 + 0];
        const float C1 = stab[6000 + l3 + 1];
        const float C2 = stab[6000 + l3 + 2];

        const float l0 = fmaf(m, A0, B0);
        const float l1 = fmaf(m, A1, B1);
        const float l2 = fmaf(m, A2, B2);
        const float mx = fmaxf(l0, fmaxf(l1, l2));
        const float e0 = __expf(l0 - mx);
        const float e1 = __expf(l1 - mx);
        const float e2 = __expf(l2 - mx);
        const float inv = 1.f / (e0 + e1 + e2);

        const float t0 = C0 * fmaf(64.f, C0, -2.f * s);
        const float t1 = C1 * fmaf(64.f, C1, -2.f * s);
        const float t2 = C2 * fmaf(64.f, C2, -2.f * s);
        acc += q + inv * (e0 * t0 + e1 * t1 + e2 * t2);

        __syncthreads();   // all reads of buf done before restage next iter
        buf ^= 1;
    }

    // block reduction
    #pragma unroll
    for (int o = 16; o > 0; o >>= 1)
        acc += __shfl_xor_sync(0xffffffffu, acc, o);
    if ((tid & 31) == 0)
        warp_acc[tid >> 5] = acc;
    __syncthreads();
    if (tid == 0) {
        float t = 0.f;
        #pragma unroll
        for (int i = 0; i < THREADS / 32; i++) t += warp_acc[i];
        g_part[bid] = t;
        __threadfence();
        unsigned int old = atomicAdd(&g_count, 1u);
        s_last = (old == GRID - 1);
    }
    __syncthreads();

    // last block finalizes: fixed-order double reduction (deterministic)
    if (s_last && tid < 32) {
        double t = 0.0;
        for (int i = tid; i < GRID; i += 32)
            t += (double)g_part[i];
        #pragma unroll
        for (int o = 16; o > 0; o >>= 1)
            t += __shfl_xor_sync(0xffffffffu, t, o);
        if (tid == 0) {
            out[0] = (float)(t / (double)B_ROWS);
            g_count = 0;   // rearm for next graph replay
        }
    }
}

extern "C" void kernel_launch(void* const* d_in, const int* in_sizes, int n_in,
                              void* d_out, int out_size)
{
    const float* x        = (const float*)d_in[0];
    const int*   labels   = (const int*)d_in[1];
    const float* lin_w    = (const float*)d_in[2];
    const float* lin_b    = (const float*)d_in[3];
    const float* linear_p = (const float*)d_in[4];
    const float* bias_p   = (const float*)d_in[5];
    const float* centers  = (const float*)d_in[6];

    cudaFuncSetAttribute(mcl_main,
                         cudaFuncAttributeMaxDynamicSharedMemorySize, SMEM_BYTES);
    mcl_main<<<GRID, THREADS, SMEM_BYTES>>>(x, labels, lin_w, lin_b,
                                            linear_p, bias_p, centers,
                                            (float*)d_out);
}